// round 1
// baseline (speedup 1.0000x reference)
#include <cuda_runtime.h>
#include <math.h>

#define T_ 2032
#define D_ 1408
#define NH_ 1408
#define NHEADS_ 16
#define HD_ 88
#define HP_ 96
#define QB_ 64
#define KB_ 64

// Scratch (allocation-free rule: device globals)
__device__ float g_q[T_ * NH_];
__device__ float g_k[T_ * NH_];
__device__ float g_v[T_ * NH_];
__device__ float g_att[T_ * NH_];

// ---------------------------------------------------------------------------
// Generic SGEMM with bias: C[M,N] = A[M,K] * B[K,N] + bias[N]
// 128x128 tile, BK=16, 256 threads, 8x8 micro-tile per thread.
// N must be a multiple of 128, K a multiple of 16 (true for all call sites).
// M is guarded.
// ---------------------------------------------------------------------------
__global__ __launch_bounds__(256)
void sgemm_bias_kernel(const float* __restrict__ A, const float* __restrict__ B,
                       const float* __restrict__ bias, float* __restrict__ C,
                       int M, int K, int N)
{
    __shared__ float As[16][128];   // transposed: As[k][m]
    __shared__ float Bs[16][128];

    const int bm = blockIdx.y * 128;
    const int bn = blockIdx.x * 128;
    const int tid = threadIdx.x;
    const int tx = tid & 15;
    const int ty = tid >> 4;

    const int arow = tid >> 2;        // 0..63
    const int acol = (tid & 3) * 4;   // 0,4,8,12
    const int brow = tid >> 5;        // 0..7
    const int bcol = (tid & 31) * 4;  // 0..124

    float acc[8][8];
#pragma unroll
    for (int i = 0; i < 8; i++)
#pragma unroll
        for (int j = 0; j < 8; j++) acc[i][j] = 0.f;

    for (int k0 = 0; k0 < K; k0 += 16) {
#pragma unroll
        for (int r = 0; r < 2; r++) {
            int row = bm + arow + r * 64;
            float4 av = make_float4(0.f, 0.f, 0.f, 0.f);
            if (row < M)
                av = *(const float4*)&A[(long)row * K + k0 + acol];
            As[acol + 0][arow + r * 64] = av.x;
            As[acol + 1][arow + r * 64] = av.y;
            As[acol + 2][arow + r * 64] = av.z;
            As[acol + 3][arow + r * 64] = av.w;
        }
#pragma unroll
        for (int r = 0; r < 2; r++) {
            *(float4*)&Bs[brow + r * 8][bcol] =
                *(const float4*)&B[(long)(k0 + brow + r * 8) * N + bn + bcol];
        }
        __syncthreads();

#pragma unroll
        for (int k = 0; k < 16; k++) {
            float a[8], b[8];
            *(float4*)&a[0] = *(const float4*)&As[k][ty * 8];
            *(float4*)&a[4] = *(const float4*)&As[k][ty * 8 + 4];
            *(float4*)&b[0] = *(const float4*)&Bs[k][tx * 8];
            *(float4*)&b[4] = *(const float4*)&Bs[k][tx * 8 + 4];
#pragma unroll
            for (int i = 0; i < 8; i++)
#pragma unroll
                for (int j = 0; j < 8; j++)
                    acc[i][j] += a[i] * b[j];
        }
        __syncthreads();
    }

#pragma unroll
    for (int i = 0; i < 8; i++) {
        int row = bm + ty * 8 + i;
        if (row >= M) continue;
#pragma unroll
        for (int j = 0; j < 8; j += 4) {
            float4 bv = *(const float4*)&bias[bn + tx * 8 + j];
            float4 cv;
            cv.x = acc[i][j + 0] + bv.x;
            cv.y = acc[i][j + 1] + bv.y;
            cv.z = acc[i][j + 2] + bv.z;
            cv.w = acc[i][j + 3] + bv.w;
            *(float4*)&C[(long)row * N + bn + tx * 8 + j] = cv;
        }
    }
}

// ---------------------------------------------------------------------------
// Interleaved RoPE applied in-place to Q and K.
// freqs_cis layout: [T, HD/2, 2] with (cos, sin).
// ---------------------------------------------------------------------------
__global__ void rope_kernel(float* __restrict__ q, float* __restrict__ k,
                            const float* __restrict__ fc)
{
    int idx = blockIdx.x * blockDim.x + threadIdx.x;
    const int total = T_ * NHEADS_ * (HD_ / 2);
    if (idx >= total) return;
    int p = idx % (HD_ / 2);
    int n = (idx / (HD_ / 2)) % NHEADS_;
    int t = idx / ((HD_ / 2) * NHEADS_);
    float c = fc[t * HD_ + 2 * p];
    float s = fc[t * HD_ + 2 * p + 1];
    long base = (long)t * NH_ + n * HD_ + 2 * p;
    float x1 = q[base], x2 = q[base + 1];
    q[base]     = x1 * c - x2 * s;
    q[base + 1] = x1 * s + x2 * c;
    x1 = k[base]; x2 = k[base + 1];
    k[base]     = x1 * c - x2 * s;
    k[base + 1] = x1 * s + x2 * c;
}

// ---------------------------------------------------------------------------
// Flash attention, fp32, non-causal. One block = one head x 64 query rows.
// 256 threads as 16x16; S micro-tile 4x4, O micro-tile 4x6 (H padded to 96).
// Online softmax; row-stat reductions via half-warp shuffles (the 16 threads
// sharing a row group are exactly one half-warp).
// ---------------------------------------------------------------------------
__global__ __launch_bounds__(256)
void attn_kernel(const float* __restrict__ Q, const float* __restrict__ K,
                 const float* __restrict__ V, float* __restrict__ O)
{
    extern __shared__ float smem[];
    float* Qs = smem;                   // [HP_][QB_]  h-major
    float* Ks = Qs + HP_ * QB_;         // [HP_][KB_]  h-major
    float* Vs = Ks + HP_ * KB_;         // [KB_][HP_]  j-major
    float* Ps = Vs + KB_ * HP_;         // [KB_][QB_]  j-major (P transposed)

    const int n = blockIdx.y;
    const int q0 = blockIdx.x * QB_;
    const int tid = threadIdx.x;
    const int tx = tid & 15;
    const int ty = tid >> 4;
    const float scale = 0.1066003581778052f;   // 88^-0.5

    // Load Q tile (h-major), zero-pad h in [88,96) and rows beyond T.
    for (int e = tid; e < QB_ * HD_; e += 256) {
        int i = e / HD_, h = e % HD_;
        int t = q0 + i;
        Qs[h * QB_ + i] = (t < T_) ? Q[(long)t * NH_ + n * HD_ + h] : 0.f;
    }
    for (int e = tid; e < QB_ * (HP_ - HD_); e += 256) {
        int i = e % QB_, h = HD_ + e / QB_;
        Qs[h * QB_ + i] = 0.f;
    }

    float m[4], l[4], acc[4][6];
#pragma unroll
    for (int r = 0; r < 4; r++) {
        m[r] = -1e30f; l[r] = 0.f;
#pragma unroll
        for (int c = 0; c < 6; c++) acc[r][c] = 0.f;
    }

    for (int s0 = 0; s0 < T_; s0 += KB_) {
        __syncthreads();   // previous-iteration consumers done (also covers Q load)
        for (int e = tid; e < KB_ * HD_; e += 256) {
            int j = e / HD_, h = e % HD_;
            int t = s0 + j;
            bool ok = (t < T_);
            Ks[h * KB_ + j] = ok ? K[(long)t * NH_ + n * HD_ + h] : 0.f;
            Vs[j * HP_ + h] = ok ? V[(long)t * NH_ + n * HD_ + h] : 0.f;
        }
        for (int e = tid; e < KB_ * (HP_ - HD_); e += 256) {
            int j = e % KB_, h = HD_ + e / KB_;
            Ks[h * KB_ + j] = 0.f;
            Vs[j * HP_ + h] = 0.f;
        }
        __syncthreads();

        // S = Q * K^T  (4x4 per thread: rows ty*4.., cols tx*4..)
        float sacc[4][4];
#pragma unroll
        for (int r = 0; r < 4; r++)
#pragma unroll
            for (int c = 0; c < 4; c++) sacc[r][c] = 0.f;

        for (int h = 0; h < HP_; h++) {
            float qa[4], kb[4];
            *(float4*)qa = *(const float4*)&Qs[h * QB_ + ty * 4];
            *(float4*)kb = *(const float4*)&Ks[h * KB_ + tx * 4];
#pragma unroll
            for (int r = 0; r < 4; r++)
#pragma unroll
                for (int c = 0; c < 4; c++)
                    sacc[r][c] += qa[r] * kb[c];
        }

        // scale + tail mask (keys beyond T)
#pragma unroll
        for (int r = 0; r < 4; r++)
#pragma unroll
            for (int c = 0; c < 4; c++) {
                float v = sacc[r][c] * scale;
                if (s0 + tx * 4 + c >= T_) v = -1e30f;
                sacc[r][c] = v;
            }

        // row max across the 16 threads of this row group (one half-warp)
        float corr[4], rsum[4];
#pragma unroll
        for (int r = 0; r < 4; r++) {
            float v = fmaxf(fmaxf(sacc[r][0], sacc[r][1]),
                            fmaxf(sacc[r][2], sacc[r][3]));
#pragma unroll
            for (int off = 1; off < 16; off <<= 1)
                v = fmaxf(v, __shfl_xor_sync(0xffffffffu, v, off));
            float mn = fmaxf(m[r], v);
            corr[r] = __expf(m[r] - mn);
            m[r] = mn;
            rsum[r] = 0.f;
        }

        // P = exp(S - m), write transposed to smem, accumulate row sums
#pragma unroll
        for (int r = 0; r < 4; r++)
#pragma unroll
            for (int c = 0; c < 4; c++) {
                float p = __expf(sacc[r][c] - m[r]);
                Ps[(tx * 4 + c) * QB_ + ty * 4 + r] = p;
                rsum[r] += p;
            }
#pragma unroll
        for (int r = 0; r < 4; r++) {
            float v = rsum[r];
#pragma unroll
            for (int off = 1; off < 16; off <<= 1)
                v += __shfl_xor_sync(0xffffffffu, v, off);
            l[r] = l[r] * corr[r] + v;
#pragma unroll
            for (int c = 0; c < 6; c++) acc[r][c] *= corr[r];
        }
        __syncthreads();   // Ps fully written

        // O += P * V   (4 rows x 6 h-cols per thread)
        for (int j = 0; j < KB_; j++) {
            float pa[4];
            *(float4*)pa = *(const float4*)&Ps[j * QB_ + ty * 4];
            float va[6];
#pragma unroll
            for (int c = 0; c < 6; c++) va[c] = Vs[j * HP_ + tx * 6 + c];
#pragma unroll
            for (int r = 0; r < 4; r++)
#pragma unroll
                for (int c = 0; c < 6; c++)
                    acc[r][c] += pa[r] * va[c];
        }
    }

    // finalize
#pragma unroll
    for (int r = 0; r < 4; r++) {
        int t = q0 + ty * 4 + r;
        if (t >= T_) continue;
        float inv = 1.f / l[r];
#pragma unroll
        for (int c = 0; c < 6; c++) {
            int h = tx * 6 + c;
            if (h < HD_)
                O[(long)t * NH_ + n * HD_ + h] = acc[r][c] * inv;
        }
    }
}

// ---------------------------------------------------------------------------
extern "C" void kernel_launch(void* const* d_in, const int* in_sizes, int n_in,
                              void* d_out, int out_size)
{
    const float* x  = (const float*)d_in[0];
    const float* fc = (const float*)d_in[1];
    const float* Wq = (const float*)d_in[2];
    const float* bq = (const float*)d_in[3];
    const float* Wk = (const float*)d_in[4];
    const float* bk = (const float*)d_in[5];
    const float* Wv = (const float*)d_in[6];
    const float* bv = (const float*)d_in[7];
    const float* Wo = (const float*)d_in[8];
    const float* bo = (const float*)d_in[9];
    float* out = (float*)d_out;

    float *qp, *kp, *vp, *ap;
    cudaGetSymbolAddress((void**)&qp, g_q);
    cudaGetSymbolAddress((void**)&kp, g_k);
    cudaGetSymbolAddress((void**)&vp, g_v);
    cudaGetSymbolAddress((void**)&ap, g_att);

    dim3 ggrid(NH_ / 128, (T_ + 127) / 128);

    // QKV projections
    sgemm_bias_kernel<<<ggrid, 256>>>(x, Wq, bq, qp, T_, D_, NH_);
    sgemm_bias_kernel<<<ggrid, 256>>>(x, Wk, bk, kp, T_, D_, NH_);
    sgemm_bias_kernel<<<ggrid, 256>>>(x, Wv, bv, vp, T_, D_, NH_);

    // RoPE on Q,K
    int ropeN = T_ * NHEADS_ * (HD_ / 2);
    rope_kernel<<<(ropeN + 255) / 256, 256>>>(qp, kp, fc);

    // Attention
    int smem = (HP_ * QB_ + HP_ * KB_ + KB_ * HP_ + KB_ * QB_) * (int)sizeof(float);
    cudaFuncSetAttribute(attn_kernel,
                         cudaFuncAttributeMaxDynamicSharedMemorySize, smem);
    attn_kernel<<<dim3((T_ + QB_ - 1) / QB_, NHEADS_), 256, smem>>>(qp, kp, vp, ap);

    // Output projection
    sgemm_bias_kernel<<<ggrid, 256>>>(ap, Wo, bo, out, T_, NH_, D_);
}

// round 3
// speedup vs baseline: 1.2754x; 1.2754x over previous
#include <cuda_runtime.h>
#include <cuda_bf16.h>
#include <cstdint>
#include <math.h>

#define T_ 2032
#define D_ 1408
#define NH_ 1408
#define NHEADS_ 16
#define HD_ 88
#define HP_ 96
#define QB_ 64
#define KB_ 64
#define GK_ 1408
#define GN_ 1408
#define NCHUNK 88            // 1408 / 16

// Scratch (allocation-free rule: device globals)
__device__ float g_q[T_ * NH_];
__device__ float g_k[T_ * NH_];
__device__ float g_v[T_ * NH_];
__device__ float g_att[T_ * NH_];

// ===========================================================================
// Warp-MMA helpers (baseline PTX — works on compute_103 target)
// ===========================================================================
__device__ __forceinline__ uint32_t smem_u32(const void* p) {
    uint32_t a;
    asm("{ .reg .u64 t; cvta.to.shared.u64 t, %1; cvt.u32.u64 %0, t; }"
        : "=r"(a) : "l"(p));
    return a;
}

__device__ __forceinline__ void ldsm_x4(uint32_t* r, uint32_t addr) {
    asm volatile("ldmatrix.sync.aligned.m8n8.x4.shared.b16 {%0,%1,%2,%3}, [%4];"
                 : "=r"(r[0]), "=r"(r[1]), "=r"(r[2]), "=r"(r[3]) : "r"(addr));
}
__device__ __forceinline__ void ldsm_x4_t(uint32_t* r, uint32_t addr) {
    asm volatile("ldmatrix.sync.aligned.m8n8.x4.trans.shared.b16 {%0,%1,%2,%3}, [%4];"
                 : "=r"(r[0]), "=r"(r[1]), "=r"(r[2]), "=r"(r[3]) : "r"(addr));
}
__device__ __forceinline__ void mma_bf16(float* d, const uint32_t* a, const uint32_t* b) {
    asm volatile(
        "mma.sync.aligned.m16n8k16.row.col.f32.bf16.bf16.f32 "
        "{%0,%1,%2,%3}, {%4,%5,%6,%7}, {%8,%9}, {%0,%1,%2,%3};"
        : "+f"(d[0]), "+f"(d[1]), "+f"(d[2]), "+f"(d[3])
        : "r"(a[0]), "r"(a[1]), "r"(a[2]), "r"(a[3]), "r"(b[0]), "r"(b[1]));
}

// split fp32 pair -> packed hi bf16x2, lo bf16x2
__device__ __forceinline__ void split2(float x, float y, uint32_t& h, uint32_t& l) {
    __nv_bfloat16 hx = __float2bfloat16_rn(x);
    __nv_bfloat16 hy = __float2bfloat16_rn(y);
    __nv_bfloat16 lx = __float2bfloat16_rn(x - __bfloat162float(hx));
    __nv_bfloat16 ly = __float2bfloat16_rn(y - __bfloat162float(hy));
    h = (uint32_t)__bfloat16_as_ushort(hx) | ((uint32_t)__bfloat16_as_ushort(hy) << 16);
    l = (uint32_t)__bfloat16_as_ushort(lx) | ((uint32_t)__bfloat16_as_ushort(ly) << 16);
}

// ===========================================================================
// HMMA GEMM: C[2032,1408] = A[2032,1408] * B[1408,1408] + bias[1408]
// B is [K][N] row-major. bf16 hi/lo 3-term split, fp32 accumulate.
// 128x128 CTA tile, BK=16, 256 threads (8 warps, each 32x64).
// A smem row stride 48B, B smem row stride 272B -> conflict-free ldmatrix.
// ===========================================================================
#define AS_STRIDE 24     // bf16 elements per A smem row (48 B)
#define BS_STRIDE 136    // bf16 elements per B smem row (272 B)

__global__ __launch_bounds__(256, 1)
void hmma_gemm_kernel(const float* __restrict__ A, const float* __restrict__ B,
                      const float* __restrict__ bias, float* __restrict__ C)
{
    __shared__ __align__(16) __nv_bfloat16 As[2][2][128 * AS_STRIDE];
    __shared__ __align__(16) __nv_bfloat16 Bs[2][2][16 * BS_STRIDE];

    const int tid = threadIdx.x;
    const int wid = tid >> 5;
    const int lane = tid & 31;
    const int wm = wid & 3;        // warp row group (32 rows)
    const int wn = wid >> 2;       // warp col group (64 cols)
    const int bm = blockIdx.y * 128;
    const int bn = blockIdx.x * 128;

    // staging assignments
    const int arow = tid >> 1;           // 0..127
    const int acol = (tid & 1) * 8;      // 0 or 8
    const int brow = tid >> 4;           // 0..15
    const int bcol = (tid & 15) * 8;     // 0..120

    const bool aok = (bm + arow) < T_;
    const float* Ag = A + (long)(bm + arow) * GK_ + acol;
    const float* Bg = B + (long)brow * GN_ + bn + bcol;

    float acc[2][8][4];
#pragma unroll
    for (int i = 0; i < 2; i++)
#pragma unroll
        for (int j = 0; j < 8; j++)
#pragma unroll
            for (int e = 0; e < 4; e++) acc[i][j][e] = 0.f;

    // prefetch chunk 0
    float4 ra0, ra1, rb0, rb1;
    {
        float4 z = make_float4(0.f, 0.f, 0.f, 0.f);
        ra0 = aok ? *(const float4*)Ag : z;
        ra1 = aok ? *(const float4*)(Ag + 4) : z;
        rb0 = *(const float4*)Bg;
        rb1 = *(const float4*)(Bg + 4);
    }

    for (int c = 0; c < NCHUNK; c++) {
        const int buf = c & 1;

        // convert + store staged regs to smem
        {
            uint4 hv, lv;
            split2(ra0.x, ra0.y, hv.x, lv.x);
            split2(ra0.z, ra0.w, hv.y, lv.y);
            split2(ra1.x, ra1.y, hv.z, lv.z);
            split2(ra1.z, ra1.w, hv.w, lv.w);
            *(uint4*)&As[buf][0][arow * AS_STRIDE + acol] = hv;
            *(uint4*)&As[buf][1][arow * AS_STRIDE + acol] = lv;
            split2(rb0.x, rb0.y, hv.x, lv.x);
            split2(rb0.z, rb0.w, hv.y, lv.y);
            split2(rb1.x, rb1.y, hv.z, lv.z);
            split2(rb1.z, rb1.w, hv.w, lv.w);
            *(uint4*)&Bs[buf][0][brow * BS_STRIDE + bcol] = hv;
            *(uint4*)&Bs[buf][1][brow * BS_STRIDE + bcol] = lv;
        }
        __syncthreads();

        // prefetch next chunk
        if (c + 1 < NCHUNK) {
            Ag += 16;
            Bg += (long)16 * GN_;
            float4 z = make_float4(0.f, 0.f, 0.f, 0.f);
            ra0 = aok ? *(const float4*)Ag : z;
            ra1 = aok ? *(const float4*)(Ag + 4) : z;
            rb0 = *(const float4*)Bg;
            rb1 = *(const float4*)(Bg + 4);
        }

        // ---- compute ----
        uint32_t ah[2][4], al[2][4], bh[4][4], bl[4][4];
        {
            uint32_t a_hi = smem_u32(&As[buf][0][0]);
            uint32_t a_lo = smem_u32(&As[buf][1][0]);
            uint32_t aoff = (uint32_t)((wm * 32 + (lane & 15)) * 48 + (lane >> 4) * 16);
#pragma unroll
            for (int i = 0; i < 2; i++) {
                ldsm_x4(ah[i], a_hi + aoff + i * 16 * 48);
                ldsm_x4(al[i], a_lo + aoff + i * 16 * 48);
            }
            uint32_t b_hi = smem_u32(&Bs[buf][0][0]);
            uint32_t b_lo = smem_u32(&Bs[buf][1][0]);
            uint32_t boff = (uint32_t)((lane & 15) * 272 + wn * 128 + (lane >> 4) * 16);
#pragma unroll
            for (int j2 = 0; j2 < 4; j2++) {
                ldsm_x4_t(bh[j2], b_hi + boff + j2 * 32);
                ldsm_x4_t(bl[j2], b_lo + boff + j2 * 32);
            }
        }
#pragma unroll
        for (int i = 0; i < 2; i++)
#pragma unroll
            for (int j = 0; j < 8; j++) {
                const uint32_t* bph = &bh[j >> 1][(j & 1) * 2];
                const uint32_t* bpl = &bl[j >> 1][(j & 1) * 2];
                mma_bf16(acc[i][j], ah[i], bph);
                mma_bf16(acc[i][j], ah[i], bpl);
                mma_bf16(acc[i][j], al[i], bph);
            }
        __syncthreads();
    }

    // epilogue
#pragma unroll
    for (int i = 0; i < 2; i++) {
        int r0 = bm + wm * 32 + i * 16 + (lane >> 2);
#pragma unroll
        for (int j = 0; j < 8; j++) {
            int cc = bn + wn * 64 + j * 8 + (lane & 3) * 2;
            float b0 = bias[cc], b1 = bias[cc + 1];
            if (r0 < T_) {
                float* p = C + (long)r0 * GN_ + cc;
                p[0] = acc[i][j][0] + b0;
                p[1] = acc[i][j][1] + b1;
            }
            if (r0 + 8 < T_) {
                float* p = C + (long)(r0 + 8) * GN_ + cc;
                p[0] = acc[i][j][2] + b0;
                p[1] = acc[i][j][3] + b1;
            }
        }
    }
}

// ---------------------------------------------------------------------------
// Interleaved RoPE applied in-place to Q and K.
// ---------------------------------------------------------------------------
__global__ void rope_kernel(float* __restrict__ q, float* __restrict__ k,
                            const float* __restrict__ fc)
{
    int idx = blockIdx.x * blockDim.x + threadIdx.x;
    const int total = T_ * NHEADS_ * (HD_ / 2);
    if (idx >= total) return;
    int p = idx % (HD_ / 2);
    int n = (idx / (HD_ / 2)) % NHEADS_;
    int t = idx / ((HD_ / 2) * NHEADS_);
    float c = fc[t * HD_ + 2 * p];
    float s = fc[t * HD_ + 2 * p + 1];
    long base = (long)t * NH_ + n * HD_ + 2 * p;
    float x1 = q[base], x2 = q[base + 1];
    q[base]     = x1 * c - x2 * s;
    q[base + 1] = x1 * s + x2 * c;
    x1 = k[base]; x2 = k[base + 1];
    k[base]     = x1 * c - x2 * s;
    k[base + 1] = x1 * s + x2 * c;
}

// ---------------------------------------------------------------------------
// Flash attention, fp32, non-causal (unchanged from passing round-1 kernel).
// ---------------------------------------------------------------------------
__global__ __launch_bounds__(256)
void attn_kernel(const float* __restrict__ Q, const float* __restrict__ K,
                 const float* __restrict__ V, float* __restrict__ O)
{
    extern __shared__ float fsm[];
    float* Qs = fsm;                    // [HP_][QB_]
    float* Ks = Qs + HP_ * QB_;         // [HP_][KB_]
    float* Vs = Ks + HP_ * KB_;         // [KB_][HP_]
    float* Ps = Vs + KB_ * HP_;         // [KB_][QB_]

    const int n = blockIdx.y;
    const int q0 = blockIdx.x * QB_;
    const int tid = threadIdx.x;
    const int tx = tid & 15;
    const int ty = tid >> 4;
    const float scale = 0.1066003581778052f;   // 88^-0.5

    for (int e = tid; e < QB_ * HD_; e += 256) {
        int i = e / HD_, h = e % HD_;
        int t = q0 + i;
        Qs[h * QB_ + i] = (t < T_) ? Q[(long)t * NH_ + n * HD_ + h] : 0.f;
    }
    for (int e = tid; e < QB_ * (HP_ - HD_); e += 256) {
        int i = e % QB_, h = HD_ + e / QB_;
        Qs[h * QB_ + i] = 0.f;
    }

    float m[4], l[4], acc[4][6];
#pragma unroll
    for (int r = 0; r < 4; r++) {
        m[r] = -1e30f; l[r] = 0.f;
#pragma unroll
        for (int c = 0; c < 6; c++) acc[r][c] = 0.f;
    }

    for (int s0 = 0; s0 < T_; s0 += KB_) {
        __syncthreads();
        for (int e = tid; e < KB_ * HD_; e += 256) {
            int j = e / HD_, h = e % HD_;
            int t = s0 + j;
            bool ok = (t < T_);
            Ks[h * KB_ + j] = ok ? K[(long)t * NH_ + n * HD_ + h] : 0.f;
            Vs[j * HP_ + h] = ok ? V[(long)t * NH_ + n * HD_ + h] : 0.f;
        }
        for (int e = tid; e < KB_ * (HP_ - HD_); e += 256) {
            int j = e % KB_, h = HD_ + e / KB_;
            Ks[h * KB_ + j] = 0.f;
            Vs[j * HP_ + h] = 0.f;
        }
        __syncthreads();

        float sacc[4][4];
#pragma unroll
        for (int r = 0; r < 4; r++)
#pragma unroll
            for (int c = 0; c < 4; c++) sacc[r][c] = 0.f;

        for (int h = 0; h < HP_; h++) {
            float qa[4], kb[4];
            *(float4*)qa = *(const float4*)&Qs[h * QB_ + ty * 4];
            *(float4*)kb = *(const float4*)&Ks[h * KB_ + tx * 4];
#pragma unroll
            for (int r = 0; r < 4; r++)
#pragma unroll
                for (int c = 0; c < 4; c++)
                    sacc[r][c] += qa[r] * kb[c];
        }

#pragma unroll
        for (int r = 0; r < 4; r++)
#pragma unroll
            for (int c = 0; c < 4; c++) {
                float v = sacc[r][c] * scale;
                if (s0 + tx * 4 + c >= T_) v = -1e30f;
                sacc[r][c] = v;
            }

        float corr[4], rsum[4];
#pragma unroll
        for (int r = 0; r < 4; r++) {
            float v = fmaxf(fmaxf(sacc[r][0], sacc[r][1]),
                            fmaxf(sacc[r][2], sacc[r][3]));
#pragma unroll
            for (int off = 1; off < 16; off <<= 1)
                v = fmaxf(v, __shfl_xor_sync(0xffffffffu, v, off));
            float mn = fmaxf(m[r], v);
            corr[r] = __expf(m[r] - mn);
            m[r] = mn;
            rsum[r] = 0.f;
        }

#pragma unroll
        for (int r = 0; r < 4; r++)
#pragma unroll
            for (int c = 0; c < 4; c++) {
                float p = __expf(sacc[r][c] - m[r]);
                Ps[(tx * 4 + c) * QB_ + ty * 4 + r] = p;
                rsum[r] += p;
            }
#pragma unroll
        for (int r = 0; r < 4; r++) {
            float v = rsum[r];
#pragma unroll
            for (int off = 1; off < 16; off <<= 1)
                v += __shfl_xor_sync(0xffffffffu, v, off);
            l[r] = l[r] * corr[r] + v;
#pragma unroll
            for (int c = 0; c < 6; c++) acc[r][c] *= corr[r];
        }
        __syncthreads();

        for (int j = 0; j < KB_; j++) {
            float pa[4];
            *(float4*)pa = *(const float4*)&Ps[j * QB_ + ty * 4];
            float va[6];
#pragma unroll
            for (int c = 0; c < 6; c++) va[c] = Vs[j * HP_ + tx * 6 + c];
#pragma unroll
            for (int r = 0; r < 4; r++)
#pragma unroll
                for (int c = 0; c < 6; c++)
                    acc[r][c] += pa[r] * va[c];
        }
    }

#pragma unroll
    for (int r = 0; r < 4; r++) {
        int t = q0 + ty * 4 + r;
        if (t >= T_) continue;
        float inv = 1.f / l[r];
#pragma unroll
        for (int c = 0; c < 6; c++) {
            int h = tx * 6 + c;
            if (h < HD_)
                O[(long)t * NH_ + n * HD_ + h] = acc[r][c] * inv;
        }
    }
}

// ---------------------------------------------------------------------------
extern "C" void kernel_launch(void* const* d_in, const int* in_sizes, int n_in,
                              void* d_out, int out_size)
{
    const float* x  = (const float*)d_in[0];
    const float* fc = (const float*)d_in[1];
    const float* Wq = (const float*)d_in[2];
    const float* bq = (const float*)d_in[3];
    const float* Wk = (const float*)d_in[4];
    const float* bk = (const float*)d_in[5];
    const float* Wv = (const float*)d_in[6];
    const float* bv = (const float*)d_in[7];
    const float* Wo = (const float*)d_in[8];
    const float* bo = (const float*)d_in[9];
    float* out = (float*)d_out;

    float *qp, *kp, *vp, *ap;
    cudaGetSymbolAddress((void**)&qp, g_q);
    cudaGetSymbolAddress((void**)&kp, g_k);
    cudaGetSymbolAddress((void**)&vp, g_v);
    cudaGetSymbolAddress((void**)&ap, g_att);

    dim3 gg(11, 16);   // (N/128, ceil(M/128))

    // QKV projections (HMMA bf16x3)
    hmma_gemm_kernel<<<gg, 256>>>(x, Wq, bq, qp);
    hmma_gemm_kernel<<<gg, 256>>>(x, Wk, bk, kp);
    hmma_gemm_kernel<<<gg, 256>>>(x, Wv, bv, vp);

    // RoPE on Q,K
    int ropeN = T_ * NHEADS_ * (HD_ / 2);
    rope_kernel<<<(ropeN + 255) / 256, 256>>>(qp, kp, fc);

    // Attention (SIMT fp32)
    int smem = (HP_ * QB_ + HP_ * KB_ + KB_ * HP_ + KB_ * QB_) * (int)sizeof(float);
    cudaFuncSetAttribute(attn_kernel,
                         cudaFuncAttributeMaxDynamicSharedMemorySize, smem);
    attn_kernel<<<dim3((T_ + QB_ - 1) / QB_, NHEADS_), 256, smem>>>(qp, kp, vp, ap);

    // Output projection (HMMA bf16x3; Wo is [N,H,D] == [1408,1408] K-major)
    hmma_gemm_kernel<<<gg, 256>>>(ap, Wo, bo, out);
}

// round 4
// speedup vs baseline: 2.5273x; 1.9816x over previous
#include <cuda_runtime.h>
#include <cuda_bf16.h>
#include <cstdint>
#include <math.h>

#define T_ 2032
#define TP_ 2048
#define D_ 1408
#define NH_ 1408
#define NHEADS_ 16
#define HD_ 88
#define HP_ 96
#define GK_ 1408
#define GN_ 1408
#define NCHUNK 88            // 1408 / 16

// Scratch (allocation-free rule: device globals)
__device__ float g_q[T_ * NH_];
__device__ float g_k[T_ * NH_];
__device__ float g_v[T_ * NH_];
__device__ float g_att[T_ * NH_];
// bf16 hi/lo split, rope-applied, padded to [2048][16][96]
#define PADSZ (TP_ * NHEADS_ * HP_)
__device__ __nv_bfloat16 g_qhi[PADSZ], g_qlo[PADSZ];
__device__ __nv_bfloat16 g_khi[PADSZ], g_klo[PADSZ];
__device__ __nv_bfloat16 g_vhi[PADSZ], g_vlo[PADSZ];

// ===========================================================================
// Helpers (baseline PTX — compute_103 safe)
// ===========================================================================
__device__ __forceinline__ uint32_t smem_u32(const void* p) {
    uint32_t a;
    asm("{ .reg .u64 t; cvta.to.shared.u64 t, %1; cvt.u32.u64 %0, t; }"
        : "=r"(a) : "l"(p));
    return a;
}
__device__ __forceinline__ void ldsm_x4(uint32_t* r, uint32_t addr) {
    asm volatile("ldmatrix.sync.aligned.m8n8.x4.shared.b16 {%0,%1,%2,%3}, [%4];"
                 : "=r"(r[0]), "=r"(r[1]), "=r"(r[2]), "=r"(r[3]) : "r"(addr));
}
__device__ __forceinline__ void ldsm_x4_t(uint32_t* r, uint32_t addr) {
    asm volatile("ldmatrix.sync.aligned.m8n8.x4.trans.shared.b16 {%0,%1,%2,%3}, [%4];"
                 : "=r"(r[0]), "=r"(r[1]), "=r"(r[2]), "=r"(r[3]) : "r"(addr));
}
__device__ __forceinline__ void mma_bf16(float* d, const uint32_t* a, const uint32_t* b) {
    asm volatile(
        "mma.sync.aligned.m16n8k16.row.col.f32.bf16.bf16.f32 "
        "{%0,%1,%2,%3}, {%4,%5,%6,%7}, {%8,%9}, {%0,%1,%2,%3};"
        : "+f"(d[0]), "+f"(d[1]), "+f"(d[2]), "+f"(d[3])
        : "r"(a[0]), "r"(a[1]), "r"(a[2]), "r"(a[3]), "r"(b[0]), "r"(b[1]));
}
__device__ __forceinline__ float ex2f(float x) {
    float y; asm("ex2.approx.f32 %0, %1;" : "=f"(y) : "f"(x)); return y;
}
__device__ __forceinline__ void cp16(uint32_t dst, const void* src) {
    asm volatile("cp.async.cg.shared.global [%0], [%1], 16;"
                 :: "r"(dst), "l"(src) : "memory");
}
#define CP_COMMIT() asm volatile("cp.async.commit_group;" ::: "memory")
#define CP_WAIT(n)  asm volatile("cp.async.wait_group %0;" :: "n"(n) : "memory")

// split fp32 pair -> packed hi bf16x2, lo bf16x2
__device__ __forceinline__ void split2(float x, float y, uint32_t& h, uint32_t& l) {
    __nv_bfloat16 hx = __float2bfloat16_rn(x);
    __nv_bfloat16 hy = __float2bfloat16_rn(y);
    __nv_bfloat16 lx = __float2bfloat16_rn(x - __bfloat162float(hx));
    __nv_bfloat16 ly = __float2bfloat16_rn(y - __bfloat162float(hy));
    h = (uint32_t)__bfloat16_as_ushort(hx) | ((uint32_t)__bfloat16_as_ushort(hy) << 16);
    l = (uint32_t)__bfloat16_as_ushort(lx) | ((uint32_t)__bfloat16_as_ushort(ly) << 16);
}

// ===========================================================================
// HMMA GEMM (unchanged from R3 — passing at rel_err 8.8e-6)
// ===========================================================================
#define AS_STRIDE 24
#define BS_STRIDE 136

__global__ __launch_bounds__(256, 1)
void hmma_gemm_kernel(const float* __restrict__ A, const float* __restrict__ B,
                      const float* __restrict__ bias, float* __restrict__ C)
{
    __shared__ __align__(16) __nv_bfloat16 As[2][2][128 * AS_STRIDE];
    __shared__ __align__(16) __nv_bfloat16 Bs[2][2][16 * BS_STRIDE];

    const int tid = threadIdx.x;
    const int wid = tid >> 5;
    const int lane = tid & 31;
    const int wm = wid & 3;
    const int wn = wid >> 2;
    const int bm = blockIdx.y * 128;
    const int bn = blockIdx.x * 128;

    const int arow = tid >> 1;
    const int acol = (tid & 1) * 8;
    const int brow = tid >> 4;
    const int bcol = (tid & 15) * 8;

    const bool aok = (bm + arow) < T_;
    const float* Ag = A + (long)(bm + arow) * GK_ + acol;
    const float* Bg = B + (long)brow * GN_ + bn + bcol;

    float acc[2][8][4];
#pragma unroll
    for (int i = 0; i < 2; i++)
#pragma unroll
        for (int j = 0; j < 8; j++)
#pragma unroll
            for (int e = 0; e < 4; e++) acc[i][j][e] = 0.f;

    float4 ra0, ra1, rb0, rb1;
    {
        float4 z = make_float4(0.f, 0.f, 0.f, 0.f);
        ra0 = aok ? *(const float4*)Ag : z;
        ra1 = aok ? *(const float4*)(Ag + 4) : z;
        rb0 = *(const float4*)Bg;
        rb1 = *(const float4*)(Bg + 4);
    }

    for (int c = 0; c < NCHUNK; c++) {
        const int buf = c & 1;
        {
            uint4 hv, lv;
            split2(ra0.x, ra0.y, hv.x, lv.x);
            split2(ra0.z, ra0.w, hv.y, lv.y);
            split2(ra1.x, ra1.y, hv.z, lv.z);
            split2(ra1.z, ra1.w, hv.w, lv.w);
            *(uint4*)&As[buf][0][arow * AS_STRIDE + acol] = hv;
            *(uint4*)&As[buf][1][arow * AS_STRIDE + acol] = lv;
            split2(rb0.x, rb0.y, hv.x, lv.x);
            split2(rb0.z, rb0.w, hv.y, lv.y);
            split2(rb1.x, rb1.y, hv.z, lv.z);
            split2(rb1.z, rb1.w, hv.w, lv.w);
            *(uint4*)&Bs[buf][0][brow * BS_STRIDE + bcol] = hv;
            *(uint4*)&Bs[buf][1][brow * BS_STRIDE + bcol] = lv;
        }
        __syncthreads();

        if (c + 1 < NCHUNK) {
            Ag += 16;
            Bg += (long)16 * GN_;
            float4 z = make_float4(0.f, 0.f, 0.f, 0.f);
            ra0 = aok ? *(const float4*)Ag : z;
            ra1 = aok ? *(const float4*)(Ag + 4) : z;
            rb0 = *(const float4*)Bg;
            rb1 = *(const float4*)(Bg + 4);
        }

        uint32_t ah[2][4], al[2][4], bh[4][4], bl[4][4];
        {
            uint32_t a_hi = smem_u32(&As[buf][0][0]);
            uint32_t a_lo = smem_u32(&As[buf][1][0]);
            uint32_t aoff = (uint32_t)((wm * 32 + (lane & 15)) * 48 + (lane >> 4) * 16);
#pragma unroll
            for (int i = 0; i < 2; i++) {
                ldsm_x4(ah[i], a_hi + aoff + i * 16 * 48);
                ldsm_x4(al[i], a_lo + aoff + i * 16 * 48);
            }
            uint32_t b_hi = smem_u32(&Bs[buf][0][0]);
            uint32_t b_lo = smem_u32(&Bs[buf][1][0]);
            uint32_t boff = (uint32_t)((lane & 15) * 272 + wn * 128 + (lane >> 4) * 16);
#pragma unroll
            for (int j2 = 0; j2 < 4; j2++) {
                ldsm_x4_t(bh[j2], b_hi + boff + j2 * 32);
                ldsm_x4_t(bl[j2], b_lo + boff + j2 * 32);
            }
        }
#pragma unroll
        for (int i = 0; i < 2; i++)
#pragma unroll
            for (int j = 0; j < 8; j++) {
                const uint32_t* bph = &bh[j >> 1][(j & 1) * 2];
                const uint32_t* bpl = &bl[j >> 1][(j & 1) * 2];
                mma_bf16(acc[i][j], ah[i], bph);
                mma_bf16(acc[i][j], ah[i], bpl);
                mma_bf16(acc[i][j], al[i], bph);
            }
        __syncthreads();
    }

#pragma unroll
    for (int i = 0; i < 2; i++) {
        int r0 = bm + wm * 32 + i * 16 + (lane >> 2);
#pragma unroll
        for (int j = 0; j < 8; j++) {
            int cc = bn + wn * 64 + j * 8 + (lane & 3) * 2;
            float b0 = bias[cc], b1 = bias[cc + 1];
            if (r0 < T_) {
                float* p = C + (long)r0 * GN_ + cc;
                p[0] = acc[i][j][0] + b0;
                p[1] = acc[i][j][1] + b1;
            }
            if (r0 + 8 < T_) {
                float* p = C + (long)(r0 + 8) * GN_ + cc;
                p[0] = acc[i][j][2] + b0;
                p[1] = acc[i][j][3] + b1;
            }
        }
    }
}

// ===========================================================================
// Prep: RoPE + fp32->bf16 hi/lo split + pad to [2048][16][96]
// ===========================================================================
__global__ void prep_kernel(const float* __restrict__ q, const float* __restrict__ k,
                            const float* __restrict__ v, const float* __restrict__ fc,
                            __nv_bfloat16* qhi, __nv_bfloat16* qlo,
                            __nv_bfloat16* khi, __nv_bfloat16* klo,
                            __nv_bfloat16* vhi, __nv_bfloat16* vlo)
{
    int idx = blockIdx.x * 256 + threadIdx.x;
    const int total = TP_ * NHEADS_ * (HP_ / 2);
    if (idx >= total) return;
    int pr = idx % 48;
    int nn = (idx / 48) & 15;
    int t  = idx / (48 * 16);
    int dst = (t * 16 + nn) * 96 + 2 * pr;

    float q1 = 0.f, q2 = 0.f, k1 = 0.f, k2 = 0.f, v1 = 0.f, v2 = 0.f;
    if (t < T_ && pr < 44) {
        long base = (long)t * NH_ + nn * HD_ + 2 * pr;
        float c = fc[t * HD_ + 2 * pr];
        float s = fc[t * HD_ + 2 * pr + 1];
        float a = q[base], b = q[base + 1];
        q1 = a * c - b * s; q2 = a * s + b * c;
        a = k[base]; b = k[base + 1];
        k1 = a * c - b * s; k2 = a * s + b * c;
        v1 = v[base]; v2 = v[base + 1];
    }
    uint32_t h, l;
    split2(q1, q2, h, l);
    *(uint32_t*)&qhi[dst] = h; *(uint32_t*)&qlo[dst] = l;
    split2(k1, k2, h, l);
    *(uint32_t*)&khi[dst] = h; *(uint32_t*)&klo[dst] = l;
    split2(v1, v2, h, l);
    *(uint32_t*)&vhi[dst] = h; *(uint32_t*)&vlo[dst] = l;
}

// ===========================================================================
// HMMA flash attention.
// CTA = (head n, 128 query rows). 8 warps x 16 rows. KV blocks of 64 keys,
// cp.async double-buffered. 3-term bf16 hi/lo MMAs, fp32 accum, ex2 softmax.
// smem layout (bytes): buf b at b*53248: khi 0, klo 13312, vhi 26624, vlo 39936
// rows: 64 x stride 208 B (104 bf16). Q staged once into buf0 (hi 0, lo 26624),
// 128 rows x 208 B.
// ===========================================================================
#define ATT_SMEM 106496
#define SSTB 208            // smem row stride bytes
#define ARRB 13312          // bytes per smem array-half
#define BUFB 53248

__global__ __launch_bounds__(256, 1)
void hmma_attn_kernel(const __nv_bfloat16* __restrict__ qhi, const __nv_bfloat16* __restrict__ qlo,
                      const __nv_bfloat16* __restrict__ khi, const __nv_bfloat16* __restrict__ klo,
                      const __nv_bfloat16* __restrict__ vhi, const __nv_bfloat16* __restrict__ vlo,
                      float* __restrict__ O)
{
    extern __shared__ char sm[];
    uint32_t sbase = smem_u32(sm);
    const int tid = threadIdx.x;
    const int wid = tid >> 5;
    const int lane = tid & 31;
    const int n = blockIdx.y;
    const int q0 = blockIdx.x * 128;
    const float sl2 = 0.15379179f;    // 88^-0.5 * log2(e)

    // ---- stage Q hi/lo into buf0 ----
#pragma unroll
    for (int it = 0; it < 12; it++) {
        int id = tid + it * 256;          // 0..3071
        int arr = id / 1536;              // 0 hi, 1 lo
        int rem = id - arr * 1536;
        int row = rem / 12;
        int c   = rem - row * 12;
        const __nv_bfloat16* src = (arr ? qlo : qhi) + ((long)(q0 + row) * 16 + n) * 96 + c * 8;
        cp16(sbase + arr * 26624 + row * SSTB + c * 16, src);
    }
    CP_COMMIT();
    CP_WAIT(0);
    __syncthreads();

    // Q fragments: rows wid*16..+15, 6 k-steps
    uint32_t qh[6][4], ql[6][4];
    {
        uint32_t qaddr = sbase + (wid * 16 + (lane & 15)) * SSTB + (lane >> 4) * 16;
#pragma unroll
        for (int kk = 0; kk < 6; kk++) {
            ldsm_x4(qh[kk], qaddr + kk * 32);
            ldsm_x4(ql[kk], qaddr + 26624 + kk * 32);
        }
    }
    __syncthreads();

    float mstat[2] = {-1e30f, -1e30f};
    float lstat[2] = {0.f, 0.f};
    float oacc[12][4];
#pragma unroll
    for (int f = 0; f < 12; f++)
#pragma unroll
        for (int e = 0; e < 4; e++) oacc[f][e] = 0.f;

    // issue KV block 0
#pragma unroll
    for (int it = 0; it < 12; it++) {
        int id = tid + it * 256;
        int arr = id / 768;
        int rem = id - arr * 768;
        int row = rem / 12;
        int c   = rem - row * 12;
        const __nv_bfloat16* src =
            (arr == 0 ? khi : arr == 1 ? klo : arr == 2 ? vhi : vlo)
            + ((long)row * 16 + n) * 96 + c * 8;
        cp16(sbase + arr * ARRB + row * SSTB + c * 16, src);
    }
    CP_COMMIT();

    for (int bi = 0; bi < 32; bi++) {
        const int buf = bi & 1;
        if (bi + 1 < 32) {
#pragma unroll
            for (int it = 0; it < 12; it++) {
                int id = tid + it * 256;
                int arr = id / 768;
                int rem = id - arr * 768;
                int row = rem / 12;
                int c   = rem - row * 12;
                const __nv_bfloat16* src =
                    (arr == 0 ? khi : arr == 1 ? klo : arr == 2 ? vhi : vlo)
                    + ((long)((bi + 1) * 64 + row) * 16 + n) * 96 + c * 8;
                cp16(sbase + (1 - buf) * BUFB + arr * ARRB + row * SSTB + c * 16, src);
            }
            CP_COMMIT();
            CP_WAIT(1);
        } else {
            CP_WAIT(0);
        }
        __syncthreads();

        // ---- S = Q K^T ----
        float sacc[8][4];
#pragma unroll
        for (int f = 0; f < 8; f++)
#pragma unroll
            for (int e = 0; e < 4; e++) sacc[f][e] = 0.f;

        uint32_t kb = sbase + buf * BUFB;
#pragma unroll
        for (int kk = 0; kk < 6; kk++) {
            uint32_t ka = kb + (lane & 15) * SSTB + (lane >> 4) * 16 + kk * 32;
#pragma unroll
            for (int j2 = 0; j2 < 4; j2++) {
                uint32_t rh[4], rl[4];
                ldsm_x4(rh, ka + j2 * (16 * SSTB));
                ldsm_x4(rl, ka + ARRB + j2 * (16 * SSTB));
                uint32_t b0h[2] = {rh[0], rh[2]}, b1h[2] = {rh[1], rh[3]};
                uint32_t b0l[2] = {rl[0], rl[2]}, b1l[2] = {rl[1], rl[3]};
                mma_bf16(sacc[2 * j2],     qh[kk], b0h);
                mma_bf16(sacc[2 * j2],     qh[kk], b0l);
                mma_bf16(sacc[2 * j2],     ql[kk], b0h);
                mma_bf16(sacc[2 * j2 + 1], qh[kk], b1h);
                mma_bf16(sacc[2 * j2 + 1], qh[kk], b1l);
                mma_bf16(sacc[2 * j2 + 1], ql[kk], b1h);
            }
        }

        // scale (log2 domain) + tail mask
#pragma unroll
        for (int f = 0; f < 8; f++)
#pragma unroll
            for (int e = 0; e < 4; e++) sacc[f][e] *= sl2;
        if (bi == 31) {
#pragma unroll
            for (int e = 0; e < 4; e++) { sacc[6][e] = -1e30f; sacc[7][e] = -1e30f; }
        }

        // ---- online softmax ----
        float mxA = -1e30f, mxB = -1e30f;
#pragma unroll
        for (int f = 0; f < 8; f++) {
            mxA = fmaxf(mxA, fmaxf(sacc[f][0], sacc[f][1]));
            mxB = fmaxf(mxB, fmaxf(sacc[f][2], sacc[f][3]));
        }
        mxA = fmaxf(mxA, __shfl_xor_sync(0xffffffffu, mxA, 1));
        mxA = fmaxf(mxA, __shfl_xor_sync(0xffffffffu, mxA, 2));
        mxB = fmaxf(mxB, __shfl_xor_sync(0xffffffffu, mxB, 1));
        mxB = fmaxf(mxB, __shfl_xor_sync(0xffffffffu, mxB, 2));
        float mA = fmaxf(mstat[0], mxA);
        float mB = fmaxf(mstat[1], mxB);
        float corrA = ex2f(mstat[0] - mA);
        float corrB = ex2f(mstat[1] - mB);
        mstat[0] = mA; mstat[1] = mB;

        float rsA = 0.f, rsB = 0.f;
#pragma unroll
        for (int f = 0; f < 8; f++) {
            sacc[f][0] = ex2f(sacc[f][0] - mA);
            sacc[f][1] = ex2f(sacc[f][1] - mA);
            sacc[f][2] = ex2f(sacc[f][2] - mB);
            sacc[f][3] = ex2f(sacc[f][3] - mB);
            rsA += sacc[f][0] + sacc[f][1];
            rsB += sacc[f][2] + sacc[f][3];
        }
        rsA += __shfl_xor_sync(0xffffffffu, rsA, 1);
        rsA += __shfl_xor_sync(0xffffffffu, rsA, 2);
        rsB += __shfl_xor_sync(0xffffffffu, rsB, 1);
        rsB += __shfl_xor_sync(0xffffffffu, rsB, 2);
        lstat[0] = lstat[0] * corrA + rsA;
        lstat[1] = lstat[1] * corrB + rsB;
#pragma unroll
        for (int f = 0; f < 12; f++) {
            oacc[f][0] *= corrA; oacc[f][1] *= corrA;
            oacc[f][2] *= corrB; oacc[f][3] *= corrB;
        }

        // ---- O += P V ----
        uint32_t vbh = kb + 2 * ARRB;
#pragma unroll
        for (int kk = 0; kk < 4; kk++) {
            // P fragments from S fragments (C->A layout identity)
            uint32_t phi[4], plo[4];
            split2(sacc[2 * kk][0],     sacc[2 * kk][1],     phi[0], plo[0]);
            split2(sacc[2 * kk][2],     sacc[2 * kk][3],     phi[1], plo[1]);
            split2(sacc[2 * kk + 1][0], sacc[2 * kk + 1][1], phi[2], plo[2]);
            split2(sacc[2 * kk + 1][2], sacc[2 * kk + 1][3], phi[3], plo[3]);

            uint32_t va = vbh + (kk * 16 + (lane & 15)) * SSTB + (lane >> 4) * 16;
#pragma unroll
            for (int j2 = 0; j2 < 6; j2++) {
                uint32_t th[4], tl[4];
                ldsm_x4_t(th, va + j2 * 32);
                ldsm_x4_t(tl, va + ARRB + j2 * 32);
                mma_bf16(oacc[2 * j2],     phi, &th[0]);
                mma_bf16(oacc[2 * j2],     phi, &tl[0]);
                mma_bf16(oacc[2 * j2],     plo, &th[0]);
                mma_bf16(oacc[2 * j2 + 1], phi, &th[2]);
                mma_bf16(oacc[2 * j2 + 1], phi, &tl[2]);
                mma_bf16(oacc[2 * j2 + 1], plo, &th[2]);
            }
        }
        __syncthreads();
    }

    // ---- finalize + store ----
    float invA = 1.f / lstat[0];
    float invB = 1.f / lstat[1];
    int rA = q0 + wid * 16 + (lane >> 2);
    int rB = rA + 8;
#pragma unroll
    for (int f = 0; f < 11; f++) {
        int h = n * HD_ + f * 8 + (lane & 3) * 2;
        if (rA < T_) {
            float* p = O + (long)rA * NH_ + h;
            p[0] = oacc[f][0] * invA;
            p[1] = oacc[f][1] * invA;
        }
        if (rB < T_) {
            float* p = O + (long)rB * NH_ + h;
            p[0] = oacc[f][2] * invB;
            p[1] = oacc[f][3] * invB;
        }
    }
}

// ---------------------------------------------------------------------------
extern "C" void kernel_launch(void* const* d_in, const int* in_sizes, int n_in,
                              void* d_out, int out_size)
{
    const float* x  = (const float*)d_in[0];
    const float* fc = (const float*)d_in[1];
    const float* Wq = (const float*)d_in[2];
    const float* bq = (const float*)d_in[3];
    const float* Wk = (const float*)d_in[4];
    const float* bk = (const float*)d_in[5];
    const float* Wv = (const float*)d_in[6];
    const float* bv = (const float*)d_in[7];
    const float* Wo = (const float*)d_in[8];
    const float* bo = (const float*)d_in[9];
    float* out = (float*)d_out;

    float *qp, *kp, *vp, *ap;
    __nv_bfloat16 *qhi, *qlo, *khi, *klo, *vhi, *vlo;
    cudaGetSymbolAddress((void**)&qp, g_q);
    cudaGetSymbolAddress((void**)&kp, g_k);
    cudaGetSymbolAddress((void**)&vp, g_v);
    cudaGetSymbolAddress((void**)&ap, g_att);
    cudaGetSymbolAddress((void**)&qhi, g_qhi);
    cudaGetSymbolAddress((void**)&qlo, g_qlo);
    cudaGetSymbolAddress((void**)&khi, g_khi);
    cudaGetSymbolAddress((void**)&klo, g_klo);
    cudaGetSymbolAddress((void**)&vhi, g_vhi);
    cudaGetSymbolAddress((void**)&vlo, g_vlo);

    dim3 gg(11, 16);

    // QKV projections (HMMA bf16x3)
    hmma_gemm_kernel<<<gg, 256>>>(x, Wq, bq, qp);
    hmma_gemm_kernel<<<gg, 256>>>(x, Wk, bk, kp);
    hmma_gemm_kernel<<<gg, 256>>>(x, Wv, bv, vp);

    // RoPE + bf16 hi/lo split + pad
    int prepN = TP_ * NHEADS_ * (HP_ / 2);
    prep_kernel<<<(prepN + 255) / 256, 256>>>(qp, kp, vp, fc,
                                              qhi, qlo, khi, klo, vhi, vlo);

    // HMMA flash attention
    cudaFuncSetAttribute(hmma_attn_kernel,
                         cudaFuncAttributeMaxDynamicSharedMemorySize, ATT_SMEM);
    hmma_attn_kernel<<<dim3(16, 16), 256, ATT_SMEM>>>(qhi, qlo, khi, klo,
                                                      vhi, vlo, ap);

    // Output projection (HMMA bf16x3)
    hmma_gemm_kernel<<<gg, 256>>>(ap, Wo, bo, out);
}

// round 5
// speedup vs baseline: 3.6968x; 1.4627x over previous
#include <cuda_runtime.h>
#include <cuda_bf16.h>
#include <cstdint>
#include <math.h>

#define T_ 2032
#define TP_ 2048
#define D_ 1408
#define NH_ 1408
#define NHEADS_ 16
#define HD_ 88
#define HP_ 96
#define GK_ 1408
#define GN_ 1408
#define NCHUNK 88            // 1408 / 16

// Scratch (allocation-free rule: device globals)
__device__ float g_q[T_ * NH_];
__device__ float g_k[T_ * NH_];
__device__ float g_v[T_ * NH_];
__device__ float g_att[T_ * NH_];
// hi/lo bf16 splits
__device__ __nv_bfloat16 g_xh[T_ * GK_], g_xl[T_ * GK_];      // x or attn-out (A operand)
__device__ __nv_bfloat16 g_ah[T_ * GK_], g_al[T_ * GK_];      // attn-out split
__device__ __nv_bfloat16 g_wh[4 * GK_ * GN_], g_wl[4 * GK_ * GN_];
// bf16 hi/lo split, rope-applied, padded to [2048][16][96]
#define PADSZ (TP_ * NHEADS_ * HP_)
__device__ __nv_bfloat16 g_qhi[PADSZ], g_qlo[PADSZ];
__device__ __nv_bfloat16 g_khi[PADSZ], g_klo[PADSZ];
__device__ __nv_bfloat16 g_vhi[PADSZ], g_vlo[PADSZ];

// ===========================================================================
// Helpers (baseline PTX — compute_103 safe)
// ===========================================================================
__device__ __forceinline__ uint32_t smem_u32(const void* p) {
    uint32_t a;
    asm("{ .reg .u64 t; cvta.to.shared.u64 t, %1; cvt.u32.u64 %0, t; }"
        : "=r"(a) : "l"(p));
    return a;
}
__device__ __forceinline__ void ldsm_x4(uint32_t* r, uint32_t addr) {
    asm volatile("ldmatrix.sync.aligned.m8n8.x4.shared.b16 {%0,%1,%2,%3}, [%4];"
                 : "=r"(r[0]), "=r"(r[1]), "=r"(r[2]), "=r"(r[3]) : "r"(addr));
}
__device__ __forceinline__ void ldsm_x4_t(uint32_t* r, uint32_t addr) {
    asm volatile("ldmatrix.sync.aligned.m8n8.x4.trans.shared.b16 {%0,%1,%2,%3}, [%4];"
                 : "=r"(r[0]), "=r"(r[1]), "=r"(r[2]), "=r"(r[3]) : "r"(addr));
}
__device__ __forceinline__ void mma_bf16(float* d, const uint32_t* a, const uint32_t* b) {
    asm volatile(
        "mma.sync.aligned.m16n8k16.row.col.f32.bf16.bf16.f32 "
        "{%0,%1,%2,%3}, {%4,%5,%6,%7}, {%8,%9}, {%0,%1,%2,%3};"
        : "+f"(d[0]), "+f"(d[1]), "+f"(d[2]), "+f"(d[3])
        : "r"(a[0]), "r"(a[1]), "r"(a[2]), "r"(a[3]), "r"(b[0]), "r"(b[1]));
}
__device__ __forceinline__ float ex2f(float x) {
    float y; asm("ex2.approx.f32 %0, %1;" : "=f"(y) : "f"(x)); return y;
}
__device__ __forceinline__ void cp16(uint32_t dst, const void* src) {
    asm volatile("cp.async.cg.shared.global [%0], [%1], 16;"
                 :: "r"(dst), "l"(src) : "memory");
}
__device__ __forceinline__ void cp16z(uint32_t dst, const void* src, uint32_t srcsz) {
    asm volatile("cp.async.cg.shared.global [%0], [%1], 16, %2;"
                 :: "r"(dst), "l"(src), "r"(srcsz) : "memory");
}
#define CP_COMMIT() asm volatile("cp.async.commit_group;" ::: "memory")
#define CP_WAIT(n)  asm volatile("cp.async.wait_group %0;" :: "n"(n) : "memory")

// split fp32 pair -> packed hi bf16x2, lo bf16x2
__device__ __forceinline__ void split2(float x, float y, uint32_t& h, uint32_t& l) {
    __nv_bfloat16 hx = __float2bfloat16_rn(x);
    __nv_bfloat16 hy = __float2bfloat16_rn(y);
    __nv_bfloat16 lx = __float2bfloat16_rn(x - __bfloat162float(hx));
    __nv_bfloat16 ly = __float2bfloat16_rn(y - __bfloat162float(hy));
    h = (uint32_t)__bfloat16_as_ushort(hx) | ((uint32_t)__bfloat16_as_ushort(hy) << 16);
    l = (uint32_t)__bfloat16_as_ushort(lx) | ((uint32_t)__bfloat16_as_ushort(ly) << 16);
}

// ===========================================================================
// fp32 -> bf16 hi/lo split (pure bandwidth)
// ===========================================================================
__global__ void split_kernel(const float* __restrict__ src,
                             __nv_bfloat16* __restrict__ hi,
                             __nv_bfloat16* __restrict__ lo, int n2)
{
    int i = blockIdx.x * 256 + threadIdx.x;
    if (i >= n2) return;
    float2 v = ((const float2*)src)[i];
    uint32_t h, l;
    split2(v.x, v.y, h, l);
    ((uint32_t*)hi)[i] = h;
    ((uint32_t*)lo)[i] = l;
}

// ===========================================================================
// HMMA GEMM v2: bf16 hi/lo inputs, cp.async staging, fused N-groups.
// C_g[2032,1408] = A[2032,1408] * B_g[1408,1408] + bias_g
// 128x128 CTA tile, BK=16, 8 warps x (32x64), 3-term split, fp32 accum.
// grid.x = 11 * ngroups (group = blockIdx.x / 11).
// ===========================================================================
struct G3 {
    const __nv_bfloat16* bh[3];
    const __nv_bfloat16* bl[3];
    const float* bias[3];
    float* c[3];
};

#define AS_ST 24     // bf16 per A smem row (48 B)
#define BS_ST 136    // bf16 per B smem row (272 B)

__global__ __launch_bounds__(256, 2)
void hmma_gemm2_kernel(const __nv_bfloat16* __restrict__ Ah,
                       const __nv_bfloat16* __restrict__ Al, G3 g)
{
    __shared__ __align__(16) __nv_bfloat16 As[2][2][128 * AS_ST];
    __shared__ __align__(16) __nv_bfloat16 Bs[2][2][16 * BS_ST];

    const int tid = threadIdx.x;
    const int wid = tid >> 5, lane = tid & 31;
    const int wm = wid & 3, wn = wid >> 2;
    const int bm = blockIdx.y * 128;
    const int which = blockIdx.x / 11;
    const int bn = (blockIdx.x - which * 11) * 128;

    const int arow = tid >> 1;
    const int acs = (tid & 1) * 8;
    const int brow = tid >> 4;
    const int bcs = (tid & 15) * 8;
    const uint32_t aok = ((bm + arow) < T_) ? 16u : 0u;

    const __nv_bfloat16* agh = Ah + (long)(bm + arow) * GK_ + acs;
    const __nv_bfloat16* agl = Al + (long)(bm + arow) * GK_ + acs;
    const __nv_bfloat16* bgh = g.bh[which] + (long)brow * GN_ + bn + bcs;
    const __nv_bfloat16* bgl = g.bl[which] + (long)brow * GN_ + bn + bcs;

    const uint32_t as0 = smem_u32(&As[0][0][0]) + (arow * AS_ST + acs) * 2;
    const uint32_t as1 = smem_u32(&As[0][1][0]) + (arow * AS_ST + acs) * 2;
    const uint32_t bs0 = smem_u32(&Bs[0][0][0]) + (brow * BS_ST + bcs) * 2;
    const uint32_t bs1 = smem_u32(&Bs[0][1][0]) + (brow * BS_ST + bcs) * 2;
    const uint32_t abuf = 2 * 128 * AS_ST * 2;   // bytes between A bufs (2 halves)
    const uint32_t bbuf = 2 * 16 * BS_ST * 2;

    float acc[2][8][4];
#pragma unroll
    for (int i = 0; i < 2; i++)
#pragma unroll
        for (int j = 0; j < 8; j++)
#pragma unroll
            for (int e = 0; e < 4; e++) acc[i][j][e] = 0.f;

    // prologue: chunk 0 -> buf 0
    cp16z(as0, agh, aok);
    cp16z(as1, agl, aok);
    cp16(bs0, bgh);
    cp16(bs1, bgl);
    CP_COMMIT();

    for (int c = 0; c < NCHUNK; c++) {
        const int buf = c & 1;
        if (c + 1 < NCHUNK) {
            const int nb = 1 - buf;
            cp16z(as0 + nb * abuf, agh + (c + 1) * 16, aok);
            cp16z(as1 + nb * abuf, agl + (c + 1) * 16, aok);
            cp16(bs0 + nb * bbuf, bgh + (long)(c + 1) * 16 * GN_);
            cp16(bs1 + nb * bbuf, bgl + (long)(c + 1) * 16 * GN_);
            CP_COMMIT();
            CP_WAIT(1);
        } else {
            CP_WAIT(0);
        }
        __syncthreads();

        uint32_t ah[2][4], al[2][4], bh[4][4], bl[4][4];
        {
            uint32_t a_hi = smem_u32(&As[buf][0][0]);
            uint32_t a_lo = smem_u32(&As[buf][1][0]);
            uint32_t aoff = (uint32_t)((wm * 32 + (lane & 15)) * 48 + (lane >> 4) * 16);
#pragma unroll
            for (int i = 0; i < 2; i++) {
                ldsm_x4(ah[i], a_hi + aoff + i * 16 * 48);
                ldsm_x4(al[i], a_lo + aoff + i * 16 * 48);
            }
            uint32_t b_hi = smem_u32(&Bs[buf][0][0]);
            uint32_t b_lo = smem_u32(&Bs[buf][1][0]);
            uint32_t boff = (uint32_t)((lane & 15) * 272 + wn * 128 + (lane >> 4) * 16);
#pragma unroll
            for (int j2 = 0; j2 < 4; j2++) {
                ldsm_x4_t(bh[j2], b_hi + boff + j2 * 32);
                ldsm_x4_t(bl[j2], b_lo + boff + j2 * 32);
            }
        }
#pragma unroll
        for (int i = 0; i < 2; i++)
#pragma unroll
            for (int j = 0; j < 8; j++) {
                const uint32_t* bph = &bh[j >> 1][(j & 1) * 2];
                const uint32_t* bpl = &bl[j >> 1][(j & 1) * 2];
                mma_bf16(acc[i][j], ah[i], bph);
                mma_bf16(acc[i][j], ah[i], bpl);
                mma_bf16(acc[i][j], al[i], bph);
            }
        __syncthreads();
    }

    const float* bias = g.bias[which];
    float* C = g.c[which];
#pragma unroll
    for (int i = 0; i < 2; i++) {
        int r0 = bm + wm * 32 + i * 16 + (lane >> 2);
#pragma unroll
        for (int j = 0; j < 8; j++) {
            int cc = bn + wn * 64 + j * 8 + (lane & 3) * 2;
            float b0 = bias[cc], b1 = bias[cc + 1];
            if (r0 < T_) {
                float* p = C + (long)r0 * GN_ + cc;
                p[0] = acc[i][j][0] + b0;
                p[1] = acc[i][j][1] + b1;
            }
            if (r0 + 8 < T_) {
                float* p = C + (long)(r0 + 8) * GN_ + cc;
                p[0] = acc[i][j][2] + b0;
                p[1] = acc[i][j][3] + b1;
            }
        }
    }
}

// ===========================================================================
// Prep: RoPE + fp32->bf16 hi/lo split + pad to [2048][16][96]
// ===========================================================================
__global__ void prep_kernel(const float* __restrict__ q, const float* __restrict__ k,
                            const float* __restrict__ v, const float* __restrict__ fc,
                            __nv_bfloat16* qhi, __nv_bfloat16* qlo,
                            __nv_bfloat16* khi, __nv_bfloat16* klo,
                            __nv_bfloat16* vhi, __nv_bfloat16* vlo)
{
    int idx = blockIdx.x * 256 + threadIdx.x;
    const int total = TP_ * NHEADS_ * (HP_ / 2);
    if (idx >= total) return;
    int pr = idx % 48;
    int nn = (idx / 48) & 15;
    int t  = idx / (48 * 16);
    int dst = (t * 16 + nn) * 96 + 2 * pr;

    float q1 = 0.f, q2 = 0.f, k1 = 0.f, k2 = 0.f, v1 = 0.f, v2 = 0.f;
    if (t < T_ && pr < 44) {
        long base = (long)t * NH_ + nn * HD_ + 2 * pr;
        float c = fc[t * HD_ + 2 * pr];
        float s = fc[t * HD_ + 2 * pr + 1];
        float a = q[base], b = q[base + 1];
        q1 = a * c - b * s; q2 = a * s + b * c;
        a = k[base]; b = k[base + 1];
        k1 = a * c - b * s; k2 = a * s + b * c;
        v1 = v[base]; v2 = v[base + 1];
    }
    uint32_t h, l;
    split2(q1, q2, h, l);
    *(uint32_t*)&qhi[dst] = h; *(uint32_t*)&qlo[dst] = l;
    split2(k1, k2, h, l);
    *(uint32_t*)&khi[dst] = h; *(uint32_t*)&klo[dst] = l;
    split2(v1, v2, h, l);
    *(uint32_t*)&vhi[dst] = h; *(uint32_t*)&vlo[dst] = l;
}

// ===========================================================================
// HMMA flash attention (unchanged from R4 — passing at 1.3e-5)
// ===========================================================================
#define ATT_SMEM 106496
#define SSTB 208
#define ARRB 13312
#define BUFB 53248

__global__ __launch_bounds__(256, 1)
void hmma_attn_kernel(const __nv_bfloat16* __restrict__ qhi, const __nv_bfloat16* __restrict__ qlo,
                      const __nv_bfloat16* __restrict__ khi, const __nv_bfloat16* __restrict__ klo,
                      const __nv_bfloat16* __restrict__ vhi, const __nv_bfloat16* __restrict__ vlo,
                      float* __restrict__ O)
{
    extern __shared__ char sm[];
    uint32_t sbase = smem_u32(sm);
    const int tid = threadIdx.x;
    const int wid = tid >> 5;
    const int lane = tid & 31;
    const int n = blockIdx.y;
    const int q0 = blockIdx.x * 128;
    const float sl2 = 0.15379179f;    // 88^-0.5 * log2(e)

#pragma unroll
    for (int it = 0; it < 12; it++) {
        int id = tid + it * 256;
        int arr = id / 1536;
        int rem = id - arr * 1536;
        int row = rem / 12;
        int c   = rem - row * 12;
        const __nv_bfloat16* src = (arr ? qlo : qhi) + ((long)(q0 + row) * 16 + n) * 96 + c * 8;
        cp16(sbase + arr * 26624 + row * SSTB + c * 16, src);
    }
    CP_COMMIT();
    CP_WAIT(0);
    __syncthreads();

    uint32_t qh[6][4], ql[6][4];
    {
        uint32_t qaddr = sbase + (wid * 16 + (lane & 15)) * SSTB + (lane >> 4) * 16;
#pragma unroll
        for (int kk = 0; kk < 6; kk++) {
            ldsm_x4(qh[kk], qaddr + kk * 32);
            ldsm_x4(ql[kk], qaddr + 26624 + kk * 32);
        }
    }
    __syncthreads();

    float mstat[2] = {-1e30f, -1e30f};
    float lstat[2] = {0.f, 0.f};
    float oacc[12][4];
#pragma unroll
    for (int f = 0; f < 12; f++)
#pragma unroll
        for (int e = 0; e < 4; e++) oacc[f][e] = 0.f;

#pragma unroll
    for (int it = 0; it < 12; it++) {
        int id = tid + it * 256;
        int arr = id / 768;
        int rem = id - arr * 768;
        int row = rem / 12;
        int c   = rem - row * 12;
        const __nv_bfloat16* src =
            (arr == 0 ? khi : arr == 1 ? klo : arr == 2 ? vhi : vlo)
            + ((long)row * 16 + n) * 96 + c * 8;
        cp16(sbase + arr * ARRB + row * SSTB + c * 16, src);
    }
    CP_COMMIT();

    for (int bi = 0; bi < 32; bi++) {
        const int buf = bi & 1;
        if (bi + 1 < 32) {
#pragma unroll
            for (int it = 0; it < 12; it++) {
                int id = tid + it * 256;
                int arr = id / 768;
                int rem = id - arr * 768;
                int row = rem / 12;
                int c   = rem - row * 12;
                const __nv_bfloat16* src =
                    (arr == 0 ? khi : arr == 1 ? klo : arr == 2 ? vhi : vlo)
                    + ((long)((bi + 1) * 64 + row) * 16 + n) * 96 + c * 8;
                cp16(sbase + (1 - buf) * BUFB + arr * ARRB + row * SSTB + c * 16, src);
            }
            CP_COMMIT();
            CP_WAIT(1);
        } else {
            CP_WAIT(0);
        }
        __syncthreads();

        float sacc[8][4];
#pragma unroll
        for (int f = 0; f < 8; f++)
#pragma unroll
            for (int e = 0; e < 4; e++) sacc[f][e] = 0.f;

        uint32_t kb = sbase + buf * BUFB;
#pragma unroll
        for (int kk = 0; kk < 6; kk++) {
            uint32_t ka = kb + (lane & 15) * SSTB + (lane >> 4) * 16 + kk * 32;
#pragma unroll
            for (int j2 = 0; j2 < 4; j2++) {
                uint32_t rh[4], rl[4];
                ldsm_x4(rh, ka + j2 * (16 * SSTB));
                ldsm_x4(rl, ka + ARRB + j2 * (16 * SSTB));
                uint32_t b0h[2] = {rh[0], rh[2]}, b1h[2] = {rh[1], rh[3]};
                uint32_t b0l[2] = {rl[0], rl[2]}, b1l[2] = {rl[1], rl[3]};
                mma_bf16(sacc[2 * j2],     qh[kk], b0h);
                mma_bf16(sacc[2 * j2],     qh[kk], b0l);
                mma_bf16(sacc[2 * j2],     ql[kk], b0h);
                mma_bf16(sacc[2 * j2 + 1], qh[kk], b1h);
                mma_bf16(sacc[2 * j2 + 1], qh[kk], b1l);
                mma_bf16(sacc[2 * j2 + 1], ql[kk], b1h);
            }
        }

#pragma unroll
        for (int f = 0; f < 8; f++)
#pragma unroll
            for (int e = 0; e < 4; e++) sacc[f][e] *= sl2;
        if (bi == 31) {
#pragma unroll
            for (int e = 0; e < 4; e++) { sacc[6][e] = -1e30f; sacc[7][e] = -1e30f; }
        }

        float mxA = -1e30f, mxB = -1e30f;
#pragma unroll
        for (int f = 0; f < 8; f++) {
            mxA = fmaxf(mxA, fmaxf(sacc[f][0], sacc[f][1]));
            mxB = fmaxf(mxB, fmaxf(sacc[f][2], sacc[f][3]));
        }
        mxA = fmaxf(mxA, __shfl_xor_sync(0xffffffffu, mxA, 1));
        mxA = fmaxf(mxA, __shfl_xor_sync(0xffffffffu, mxA, 2));
        mxB = fmaxf(mxB, __shfl_xor_sync(0xffffffffu, mxB, 1));
        mxB = fmaxf(mxB, __shfl_xor_sync(0xffffffffu, mxB, 2));
        float mA = fmaxf(mstat[0], mxA);
        float mB = fmaxf(mstat[1], mxB);
        float corrA = ex2f(mstat[0] - mA);
        float corrB = ex2f(mstat[1] - mB);
        mstat[0] = mA; mstat[1] = mB;

        float rsA = 0.f, rsB = 0.f;
#pragma unroll
        for (int f = 0; f < 8; f++) {
            sacc[f][0] = ex2f(sacc[f][0] - mA);
            sacc[f][1] = ex2f(sacc[f][1] - mA);
            sacc[f][2] = ex2f(sacc[f][2] - mB);
            sacc[f][3] = ex2f(sacc[f][3] - mB);
            rsA += sacc[f][0] + sacc[f][1];
            rsB += sacc[f][2] + sacc[f][3];
        }
        rsA += __shfl_xor_sync(0xffffffffu, rsA, 1);
        rsA += __shfl_xor_sync(0xffffffffu, rsA, 2);
        rsB += __shfl_xor_sync(0xffffffffu, rsB, 1);
        rsB += __shfl_xor_sync(0xffffffffu, rsB, 2);
        lstat[0] = lstat[0] * corrA + rsA;
        lstat[1] = lstat[1] * corrB + rsB;
#pragma unroll
        for (int f = 0; f < 12; f++) {
            oacc[f][0] *= corrA; oacc[f][1] *= corrA;
            oacc[f][2] *= corrB; oacc[f][3] *= corrB;
        }

        uint32_t vbh = kb + 2 * ARRB;
#pragma unroll
        for (int kk = 0; kk < 4; kk++) {
            uint32_t phi[4], plo[4];
            split2(sacc[2 * kk][0],     sacc[2 * kk][1],     phi[0], plo[0]);
            split2(sacc[2 * kk][2],     sacc[2 * kk][3],     phi[1], plo[1]);
            split2(sacc[2 * kk + 1][0], sacc[2 * kk + 1][1], phi[2], plo[2]);
            split2(sacc[2 * kk + 1][2], sacc[2 * kk + 1][3], phi[3], plo[3]);

            uint32_t va = vbh + (kk * 16 + (lane & 15)) * SSTB + (lane >> 4) * 16;
#pragma unroll
            for (int j2 = 0; j2 < 6; j2++) {
                uint32_t th[4], tl[4];
                ldsm_x4_t(th, va + j2 * 32);
                ldsm_x4_t(tl, va + ARRB + j2 * 32);
                mma_bf16(oacc[2 * j2],     phi, &th[0]);
                mma_bf16(oacc[2 * j2],     phi, &tl[0]);
                mma_bf16(oacc[2 * j2],     plo, &th[0]);
                mma_bf16(oacc[2 * j2 + 1], phi, &th[2]);
                mma_bf16(oacc[2 * j2 + 1], phi, &tl[2]);
                mma_bf16(oacc[2 * j2 + 1], plo, &th[2]);
            }
        }
        __syncthreads();
    }

    float invA = 1.f / lstat[0];
    float invB = 1.f / lstat[1];
    int rA = q0 + wid * 16 + (lane >> 2);
    int rB = rA + 8;
#pragma unroll
    for (int f = 0; f < 11; f++) {
        int h = n * HD_ + f * 8 + (lane & 3) * 2;
        if (rA < T_) {
            float* p = O + (long)rA * NH_ + h;
            p[0] = oacc[f][0] * invA;
            p[1] = oacc[f][1] * invA;
        }
        if (rB < T_) {
            float* p = O + (long)rB * NH_ + h;
            p[0] = oacc[f][2] * invB;
            p[1] = oacc[f][3] * invB;
        }
    }
}

// ---------------------------------------------------------------------------
extern "C" void kernel_launch(void* const* d_in, const int* in_sizes, int n_in,
                              void* d_out, int out_size)
{
    const float* x  = (const float*)d_in[0];
    const float* fc = (const float*)d_in[1];
    const float* Wq = (const float*)d_in[2];
    const float* bq = (const float*)d_in[3];
    const float* Wk = (const float*)d_in[4];
    const float* bk = (const float*)d_in[5];
    const float* Wv = (const float*)d_in[6];
    const float* bv = (const float*)d_in[7];
    const float* Wo = (const float*)d_in[8];
    const float* bo = (const float*)d_in[9];
    float* out = (float*)d_out;

    float *qp, *kp, *vp, *ap;
    __nv_bfloat16 *xh, *xl, *ah, *al, *wh, *wl;
    __nv_bfloat16 *qhi, *qlo, *khi, *klo, *vhi, *vlo;
    cudaGetSymbolAddress((void**)&qp, g_q);
    cudaGetSymbolAddress((void**)&kp, g_k);
    cudaGetSymbolAddress((void**)&vp, g_v);
    cudaGetSymbolAddress((void**)&ap, g_att);
    cudaGetSymbolAddress((void**)&xh, g_xh);
    cudaGetSymbolAddress((void**)&xl, g_xl);
    cudaGetSymbolAddress((void**)&ah, g_ah);
    cudaGetSymbolAddress((void**)&al, g_al);
    cudaGetSymbolAddress((void**)&wh, g_wh);
    cudaGetSymbolAddress((void**)&wl, g_wl);
    cudaGetSymbolAddress((void**)&qhi, g_qhi);
    cudaGetSymbolAddress((void**)&qlo, g_qlo);
    cudaGetSymbolAddress((void**)&khi, g_khi);
    cudaGetSymbolAddress((void**)&klo, g_klo);
    cudaGetSymbolAddress((void**)&vhi, g_vhi);
    cudaGetSymbolAddress((void**)&vlo, g_vlo);

    const long WSZ = (long)GK_ * GN_;
    const int n2x = T_ * GK_ / 2;
    const int n2w = (int)(WSZ / 2);

    // splits
    split_kernel<<<(n2x + 255) / 256, 256>>>(x,  xh, xl, n2x);
    split_kernel<<<(n2w + 255) / 256, 256>>>(Wq, wh + 0 * WSZ, wl + 0 * WSZ, n2w);
    split_kernel<<<(n2w + 255) / 256, 256>>>(Wk, wh + 1 * WSZ, wl + 1 * WSZ, n2w);
    split_kernel<<<(n2w + 255) / 256, 256>>>(Wv, wh + 2 * WSZ, wl + 2 * WSZ, n2w);
    split_kernel<<<(n2w + 255) / 256, 256>>>(Wo, wh + 3 * WSZ, wl + 3 * WSZ, n2w);

    // fused QKV GEMM (grid 33x16)
    G3 gq;
    gq.bh[0] = wh + 0 * WSZ; gq.bl[0] = wl + 0 * WSZ; gq.bias[0] = bq; gq.c[0] = qp;
    gq.bh[1] = wh + 1 * WSZ; gq.bl[1] = wl + 1 * WSZ; gq.bias[1] = bk; gq.c[1] = kp;
    gq.bh[2] = wh + 2 * WSZ; gq.bl[2] = wl + 2 * WSZ; gq.bias[2] = bv; gq.c[2] = vp;
    hmma_gemm2_kernel<<<dim3(33, 16), 256>>>(xh, xl, gq);

    // RoPE + split + pad
    int prepN = TP_ * NHEADS_ * (HP_ / 2);
    prep_kernel<<<(prepN + 255) / 256, 256>>>(qp, kp, vp, fc,
                                              qhi, qlo, khi, klo, vhi, vlo);

    // HMMA flash attention
    cudaFuncSetAttribute(hmma_attn_kernel,
                         cudaFuncAttributeMaxDynamicSharedMemorySize, ATT_SMEM);
    hmma_attn_kernel<<<dim3(16, 16), 256, ATT_SMEM>>>(qhi, qlo, khi, klo,
                                                      vhi, vlo, ap);

    // split attention output, then out-proj
    split_kernel<<<(n2x + 255) / 256, 256>>>(ap, ah, al, n2x);
    G3 go;
    go.bh[0] = wh + 3 * WSZ; go.bl[0] = wl + 3 * WSZ; go.bias[0] = bo; go.c[0] = out;
    go.bh[1] = go.bh[0]; go.bl[1] = go.bl[0]; go.bias[1] = bo; go.c[1] = out;
    go.bh[2] = go.bh[0]; go.bl[2] = go.bl[0]; go.bias[2] = bo; go.c[2] = out;
    hmma_gemm2_kernel<<<dim3(11, 16), 256>>>(ah, al, go);
}